// round 16
// baseline (speedup 1.0000x reference)
#include <cuda_runtime.h>
#include <cuda_bf16.h>
#include <math.h>
#include <stdint.h>

#define N_NODES 20000
#define N_EDGES 200000
#define CH 64
#define HC 256
#define NHEAD 4
#define NTILES64 3125

// ---------------- scratch ----------------
__device__ __align__(256) float    g_h[N_NODES * CH];
__device__ __align__(256) __nv_bfloat16 g_hs[N_NODES * 128];
__device__ __align__(256) __nv_bfloat16 g_fs[N_EDGES * 128];
__device__ __align__(256) __nv_bfloat16 g_es[N_EDGES * 48];
__device__ __align__(256) __nv_bfloat16 g_wprep[8 * 256 * 192];
__device__ __align__(256) __nv_bfloat16 g_wce0[256 * 48];
__device__ __align__(256) float    g_bce0[256];
__device__ __align__(256) float    g_hni[N_NODES * HC];
__device__ __align__(256) float    g_hnj[N_NODES * HC];
__device__ __align__(256) float    g_hproj[N_NODES * HC];
__device__ __align__(256) float    g_score[N_EDGES * NHEAD];
__device__ __align__(256) int g_deg[N_NODES];
__device__ __align__(256) int g_off[N_NODES + 1];
__device__ __align__(256) int g_cursor[N_NODES];
__device__ __align__(256) int g_eidx[N_EDGES];

// ---------------- helpers ----------------
__device__ __forceinline__ uint32_t smem_u32(const void* p) {
    uint32_t a;
    asm("{ .reg .u64 t; cvta.to.shared.u64 t, %1; cvt.u32.u64 %0, t; }" : "=r"(a) : "l"(p));
    return a;
}
__device__ __forceinline__ float eluf(float x) { return x > 0.f ? x : expm1f(x); }
__device__ __forceinline__ float warp_sum(float v) {
#pragma unroll
    for (int o = 16; o; o >>= 1) v += __shfl_xor_sync(0xffffffffu, v, o);
    return v;
}
__device__ __forceinline__ float warp_max(float v) {
#pragma unroll
    for (int o = 16; o; o >>= 1) v = fmaxf(v, __shfl_xor_sync(0xffffffffu, v, o));
    return v;
}
__device__ __forceinline__ void ldm_x4(uint32_t* r, uint32_t addr) {
    asm volatile("ldmatrix.sync.aligned.m8n8.x4.shared.b16 {%0,%1,%2,%3}, [%4];"
                 : "=r"(r[0]), "=r"(r[1]), "=r"(r[2]), "=r"(r[3]) : "r"(addr));
}
__device__ __forceinline__ void mma_bf16(float* d, const uint32_t* a, const uint32_t* b) {
    asm volatile("mma.sync.aligned.m16n8k16.row.col.f32.bf16.bf16.f32 "
                 "{%0,%1,%2,%3}, {%4,%5,%6,%7}, {%8,%9}, {%0,%1,%2,%3};"
                 : "+f"(d[0]), "+f"(d[1]), "+f"(d[2]), "+f"(d[3])
                 : "r"(a[0]), "r"(a[1]), "r"(a[2]), "r"(a[3]), "r"(b[0]), "r"(b[1]));
}
#define GBAR(id) asm volatile("bar.sync %0, 256;" :: "r"(id) : "memory")

#define MM_SMEM 153600

// ======== non-persistent mma tile (node GEMMs) ========
template<int KSTEPS, int HSPLIT>
__device__ __forceinline__ void mma_tile_to_stage(
    char* smem, const __nv_bfloat16* __restrict__ A, const __nv_bfloat16* __restrict__ Wp,
    int row0, int M, int tid, int w, int lane) {
    constexpr int KELEM = KSTEPS * 16;
    constexpr int STRIDE = KELEM + 8;
    constexpr int AROW = HSPLIT ? 2 * HSPLIT : KELEM;
    constexpr int CPR = KELEM / 8;
    constexpr int TILEB = 16 * STRIDE * 2;
    __nv_bfloat16* smA = (__nv_bfloat16*)smem;
    __nv_bfloat16* smB = (__nv_bfloat16*)(smem + 128 * STRIDE * 2);

    for (int u = tid; u < 128 * CPR; u += 512) {
        int m = u / CPR, k0 = (u % CPR) * 8;
        int sc = (HSPLIT && k0 >= HSPLIT) ? k0 - HSPLIT : k0;
        int mm = row0 + m < M ? row0 + m : M - 1;
        int bytes = (row0 + m < M) ? 16 : 0;
        uint32_t sa = smem_u32(smA + m * STRIDE + k0);
        asm volatile("cp.async.cg.shared.global [%0], [%1], 16, %2;"
                     :: "r"(sa), "l"(A + (size_t)mm * AROW + sc), "r"(bytes));
    }
    for (int u = tid; u < 256 * CPR; u += 512) {
        int n = u / CPR, k0 = (u % CPR) * 8;
        uint32_t sa = smem_u32(smB + n * STRIDE + k0);
        asm volatile("cp.async.cg.shared.global [%0], [%1], 16;"
                     :: "r"(sa), "l"(Wp + (size_t)n * KELEM + k0));
    }
    asm volatile("cp.async.commit_group;");
    asm volatile("cp.async.wait_group 0;" ::: "memory");
    __syncthreads();

    const int mw = (w >> 3) * 64;
    const int nw = (w & 7) * 32;
    const int g = lane >> 3, r = lane & 7;

    float acc[4][4][4];
#pragma unroll
    for (int i = 0; i < 4; i++)
#pragma unroll
        for (int j = 0; j < 4; j++)
#pragma unroll
            for (int q = 0; q < 4; q++) acc[i][j][q] = 0.f;

    uint32_t aAddr = smem_u32(smA) + ((mw + (g & 1) * 8 + r) * STRIDE + (g >> 1) * 8) * 2;
    uint32_t bAddr = smem_u32(smB) + ((nw + (g >> 1) * 8 + r) * STRIDE + (g & 1) * 8) * 2;

#pragma unroll
    for (int ks = 0; ks < KSTEPS; ks++) {
        uint32_t af[4][4], bf[2][4];
#pragma unroll
        for (int i = 0; i < 4; i++) ldm_x4(af[i], aAddr + i * TILEB);
#pragma unroll
        for (int p = 0; p < 2; p++) ldm_x4(bf[p], bAddr + p * TILEB);
#pragma unroll
        for (int i = 0; i < 4; i++)
#pragma unroll
            for (int j = 0; j < 4; j++)
                mma_bf16(acc[i][j], af[i], &bf[j >> 1][(j & 1) * 2]);
        aAddr += 32;
        bAddr += 32;
    }

    __syncthreads();
    float* stage = (float*)smem;
#pragma unroll
    for (int i = 0; i < 4; i++)
#pragma unroll
        for (int j = 0; j < 4; j++) {
            int m = mw + i * 16 + (lane >> 2);
            int n = nw + j * 8 + (lane & 3) * 2;
            stage[m * 260 + n] = acc[i][j][0];
            stage[m * 260 + n + 1] = acc[i][j][1];
            stage[(m + 8) * 260 + n] = acc[i][j][2];
            stage[(m + 8) * 260 + n + 1] = acc[i][j][3];
        }
}

// ======== node GEMMs: ni, nj, node(hproj)+bias ========
__global__ void __launch_bounds__(512, 1)
gemm_node3(const __nv_bfloat16* __restrict__ A, const __nv_bfloat16* __restrict__ WpBase,
           const float* __restrict__ bnode_l,
           float* __restrict__ Cni, float* __restrict__ Cnj, float* __restrict__ Cnode) {
    extern __shared__ __align__(1024) char smem[];
    const int tid = threadIdx.x, w = tid >> 5, lane = tid & 31;
    const int row0 = blockIdx.x * 128;
    const int y = blockIdx.y;
    const __nv_bfloat16* Wp = WpBase + (size_t)y * (256 * 192);
    float* C = (y == 0) ? Cni : (y == 1) ? Cnj : Cnode;
    const float* bias = (y == 2) ? bnode_l : nullptr;

    mma_tile_to_stage<12, 64>(smem, A, Wp, row0, N_NODES, tid, w, lane);
    __syncthreads();

    float* stage = (float*)smem;
    int rows = min(128, N_NODES - row0);
    for (int u = tid; u < rows * 64; u += 512) {
        int m2 = u >> 6, c4 = (u & 63) * 4;
        float4 v = *(float4*)(stage + m2 * 260 + c4);
        if (bias) {
            float4 bb = *(const float4*)(bias + c4);
            v.x += bb.x; v.y += bb.y; v.z += bb.z; v.w += bb.w;
        }
        *(float4*)(C + (size_t)(row0 + m2) * 256 + c4) = v;
    }
}

// ======== batch-2 per-edge finisher ========
__device__ __forceinline__ void edge_finish2(
    int e0, int e1, bool ok1, float* v0, float* v1,
    const float* sAttn, int lane, int writeF) {
    float p[2][NHEAD];
#pragma unroll
    for (int h = 0; h < NHEAD; h++) {
        float a0 = sAttn[h * 64 + lane];
        float a1 = sAttn[h * 64 + lane + 32];
        float x00 = v0[2 * h], x01 = v0[2 * h + 1];
        float x10 = v1[2 * h], x11 = v1[2 * h + 1];
        float l00 = x00 > 0.f ? x00 : 0.01f * x00;
        float l01 = x01 > 0.f ? x01 : 0.01f * x01;
        float l10 = x10 > 0.f ? x10 : 0.01f * x10;
        float l11 = x11 > 0.f ? x11 : 0.01f * x11;
        p[0][h] = l00 * a0 + l01 * a1;
        p[1][h] = l10 * a0 + l11 * a1;
    }
#pragma unroll
    for (int o = 16; o; o >>= 1)
#pragma unroll
        for (int q = 0; q < 2; q++)
#pragma unroll
            for (int h = 0; h < NHEAD; h++)
                p[q][h] += __shfl_xor_sync(0xffffffffu, p[q][h], o);
    if (lane < NHEAD) {
        g_score[e0 * NHEAD + lane] = p[0][lane];
        if (ok1) g_score[e1 * NHEAD + lane] = p[1][lane];
    }

    if (writeF) {
        float m00 = 0.25f * (v0[0] + v0[2] + v0[4] + v0[6]);
        float m01 = 0.25f * (v0[1] + v0[3] + v0[5] + v0[7]);
        float m10 = 0.25f * (v1[0] + v1[2] + v1[4] + v1[6]);
        float m11 = 0.25f * (v1[1] + v1[3] + v1[5] + v1[7]);
        float su0 = m00 + m01, sq0 = m00 * m00 + m01 * m01;
        float su1 = m10 + m11, sq1 = m10 * m10 + m11 * m11;
#pragma unroll
        for (int o = 16; o; o >>= 1) {
            su0 += __shfl_xor_sync(0xffffffffu, su0, o);
            sq0 += __shfl_xor_sync(0xffffffffu, sq0, o);
            su1 += __shfl_xor_sync(0xffffffffu, su1, o);
            sq1 += __shfl_xor_sync(0xffffffffu, sq1, o);
        }
        {
            float mean = su0 * (1.f / 64.f);
            float var = sq0 * (1.f / 64.f) - mean * mean;
            float rs = rsqrtf(var + 1e-5f);
            float f0 = eluf((m00 - mean) * rs);
            float f1 = eluf((m01 - mean) * rs);
            __nv_bfloat16 h0 = __float2bfloat16(f0);
            __nv_bfloat16 h1 = __float2bfloat16(f1);
            size_t b = (size_t)e0 * 128;
            g_fs[b + lane] = h0;
            g_fs[b + lane + 32] = h1;
            g_fs[b + 64 + lane] = __float2bfloat16(f0 - __bfloat162float(h0));
            g_fs[b + 96 + lane] = __float2bfloat16(f1 - __bfloat162float(h1));
        }
        if (ok1) {
            float mean = su1 * (1.f / 64.f);
            float var = sq1 * (1.f / 64.f) - mean * mean;
            float rs = rsqrtf(var + 1e-5f);
            float f0 = eluf((m10 - mean) * rs);
            float f1 = eluf((m11 - mean) * rs);
            __nv_bfloat16 h0 = __float2bfloat16(f0);
            __nv_bfloat16 h1 = __float2bfloat16(f1);
            size_t b = (size_t)e1 * 128;
            g_fs[b + lane] = h0;
            g_fs[b + lane + 32] = h1;
            g_fs[b + 64 + lane] = __float2bfloat16(f0 - __bfloat162float(h0));
            g_fs[b + 96 + lane] = __float2bfloat16(f1 - __bfloat162float(h1));
        }
    }
}

// ======== DUAL-GROUP persistent edge GEMM: pipelined gather epilogue ========
template<int KSTEPS, int HSPLIT>
__global__ void __launch_bounds__(512)
gemm_edge_g2(const __nv_bfloat16* __restrict__ A, const __nv_bfloat16* __restrict__ Wp,
             const float* __restrict__ bias_e_l, const float* __restrict__ attn_l,
             const int* __restrict__ src, const int* __restrict__ dst,
             int numTiles, int writeF) {
    constexpr int KELEM = KSTEPS * 16;
    constexpr int STRIDE = KELEM + 8;
    constexpr int AROW = HSPLIT ? 2 * HSPLIT : KELEM;
    constexpr int CPR = KELEM / 8;
    constexpr int TILEB = 16 * STRIDE * 2;
    constexpr int OFF_G = 256 * STRIDE * 2;
    constexpr int ASZ = 64 * STRIDE * 2;
    constexpr int GSZ = ASZ + 33280 + 1024;
    constexpr int OFF_ATTN = OFF_G + 2 * GSZ;
    constexpr int OFF_BIAS = OFF_ATTN + 1024;
    extern __shared__ __align__(1024) char smem[];
    const int tid = threadIdx.x;
    const int grp = tid >> 8;
    const int gtid = tid & 255;
    const int lw = (tid >> 5) & 7;
    const int lane = tid & 31;

    __nv_bfloat16* smB = (__nv_bfloat16*)smem;
    char* gbase = smem + OFF_G + grp * GSZ;
    __nv_bfloat16* smA = (__nv_bfloat16*)gbase;
    float* stage = (float*)(gbase + ASZ);
    int* sSrc = (int*)(gbase + ASZ + 33280);
    int* sDst = sSrc + 128;
    float* sAttn = (float*)(smem + OFF_ATTN);
    float* sBias = (float*)(smem + OFF_BIAS);

    for (int u = tid; u < 256 * CPR; u += 512) {
        int n = u / CPR, k0 = (u % CPR) * 8;
        uint32_t sa = smem_u32(smB + n * STRIDE + k0);
        asm volatile("cp.async.cg.shared.global [%0], [%1], 16;"
                     :: "r"(sa), "l"(Wp + (size_t)n * KELEM + k0));
    }
    if (tid < 256) sAttn[tid] = attn_l[tid];
    else sBias[tid - 256] = bias_e_l[tid - 256];

    auto fillA = [&](int t, int par) {
        int row0 = t * 64;
        for (int u = gtid; u < 64 * CPR; u += 256) {
            int m = u / CPR, k0 = (u % CPR) * 8;
            int sc = (HSPLIT && k0 >= HSPLIT) ? k0 - HSPLIT : k0;
            int mm = row0 + m < N_EDGES ? row0 + m : N_EDGES - 1;
            int bytes = (row0 + m < N_EDGES) ? 16 : 0;
            uint32_t sa = smem_u32(smA + m * STRIDE + k0);
            asm volatile("cp.async.cg.shared.global [%0], [%1], 16, %2;"
                         :: "r"(sa), "l"(A + (size_t)mm * AROW + sc), "r"(bytes));
        }
        if (gtid < 32) {
            int c = gtid & 15;
            int isd = gtid >> 4;
            const int* gp = isd ? dst : src;
            int eo = row0 + c * 4;
            int bytes = (eo + 4 <= N_EDGES) ? 16 : 0;
            int eoc = eo + 4 <= N_EDGES ? eo : 0;
            uint32_t sa = smem_u32((isd ? sDst : sSrc) + par * 64 + c * 4);
            asm volatile("cp.async.ca.shared.global [%0], [%1], 16, %2;"
                         :: "r"(sa), "l"(gp + eoc), "r"(bytes));
        }
        asm volatile("cp.async.commit_group;");
    };

    const int stride = gridDim.x * 2;
    int t = blockIdx.x * 2 + grp;
    int par = 0;
    if (t < numTiles) fillA(t, par);
    else asm volatile("cp.async.commit_group;");
    asm volatile("cp.async.wait_group 0;" ::: "memory");
    __syncthreads();

    const int mw = (lw >> 2) * 32;
    const int nw = (lw & 3) * 64;
    const int l8 = lane >> 3, r = lane & 7;
    const int barid = 1 + grp;

    for (; t < numTiles; t += stride) {
        int row0 = t * 64;

        float acc[2][8][4];
#pragma unroll
        for (int i = 0; i < 2; i++)
#pragma unroll
            for (int j = 0; j < 8; j++)
#pragma unroll
                for (int q = 0; q < 4; q++) acc[i][j][q] = 0.f;

        uint32_t aAddr = smem_u32(smA) + ((mw + (l8 & 1) * 8 + r) * STRIDE + (l8 >> 1) * 8) * 2;
        uint32_t bAddr = smem_u32(smB) + ((nw + (l8 >> 1) * 8 + r) * STRIDE + (l8 & 1) * 8) * 2;
#pragma unroll
        for (int ks = 0; ks < KSTEPS; ks++) {
            uint32_t af[2][4], bf[4][4];
#pragma unroll
            for (int i = 0; i < 2; i++) ldm_x4(af[i], aAddr + i * TILEB);
#pragma unroll
            for (int p = 0; p < 4; p++) ldm_x4(bf[p], bAddr + p * TILEB);
#pragma unroll
            for (int i = 0; i < 2; i++)
#pragma unroll
                for (int j = 0; j < 8; j++)
                    mma_bf16(acc[i][j], af[i], &bf[j >> 1][(j & 1) * 2]);
            aAddr += 32;
            bAddr += 32;
        }
        GBAR(barid);

        int nxt = t + stride;
        if (nxt < numTiles) fillA(nxt, par ^ 1);

#pragma unroll
        for (int c = 0; c < 2; c++) {
            if ((lw >> 2) == c) {
#pragma unroll
                for (int i = 0; i < 2; i++)
#pragma unroll
                    for (int j = 0; j < 8; j++) {
                        int m = i * 16 + (lane >> 2);
                        int n = nw + j * 8 + (lane & 3) * 2;
                        stage[m * 260 + n] = acc[i][j][0];
                        stage[m * 260 + n + 1] = acc[i][j][1];
                        stage[(m + 8) * 260 + n] = acc[i][j][2];
                        stage[(m + 8) * 260 + n + 1] = acc[i][j][3];
                    }
            }
            GBAR(barid);

            // pipelined epilogue: gather all 4 edges first, then run both finishers
            {
                int base_el = c * 32 + lw * 4;
                int e0 = row0 + base_el;
                if (e0 < N_EDGES) {
                    int e1 = e0 + 1, e2 = e0 + 2, e3 = e0 + 3;
                    bool ok1 = e1 < N_EDGES, ok2 = e2 < N_EDGES, ok3 = e3 < N_EDGES;
                    const float* pni[4];
                    const float* pnj[4];
#pragma unroll
                    for (int q = 0; q < 4; q++) {
                        int el = base_el + q;
                        int ss = sSrc[par * 64 + el], dd = sDst[par * 64 + el];
                        pni[q] = g_hni + (size_t)ss * HC;
                        pnj[q] = g_hnj + (size_t)dd * HC;
                    }
                    float v[4][8];
#pragma unroll
                    for (int j = 0; j < 8; j++) {
                        int cc = lane + 32 * j;
                        float bb = sBias[cc];
#pragma unroll
                        for (int q = 0; q < 4; q++)
                            v[q][j] = stage[(lw * 4 + q) * 260 + cc] + pni[q][cc] + pnj[q][cc] + bb;
                    }
                    edge_finish2(e0, e1, ok1, v[0], v[1], sAttn, lane, writeF);
                    if (ok2) edge_finish2(e2, e3, ok3, v[2], v[3], sAttn, lane, writeF);
                }
            }
            GBAR(barid);
        }

        if (nxt < numTiles) {
            asm volatile("cp.async.wait_group 0;" ::: "memory");
        }
        GBAR(barid);
        par ^= 1;
    }
}

// ======== node gather ========
__global__ void __launch_bounds__(256)
node_gather(const int* __restrict__ src) {
    int n = (blockIdx.x * blockDim.x + threadIdx.x) >> 5;
    if (n >= N_NODES) return;
    int lane = threadIdx.x & 31;
    int off0 = g_off[n], off1 = g_off[n + 1];

    float h0 = 0.f, h1 = 0.f;
    if (off0 < off1) {
        float mx0 = -1e30f, mx1 = -1e30f, mx2 = -1e30f, mx3 = -1e30f;
        for (int i = off0 + lane; i < off1; i += 32) {
            int e = g_eidx[i];
            float4 s = *(const float4*)(g_score + (size_t)e * 4);
            mx0 = fmaxf(mx0, s.x); mx1 = fmaxf(mx1, s.y);
            mx2 = fmaxf(mx2, s.z); mx3 = fmaxf(mx3, s.w);
        }
        mx0 = warp_max(mx0); mx1 = warp_max(mx1);
        mx2 = warp_max(mx2); mx3 = warp_max(mx3);

        float den0 = 0.f, den1 = 0.f, den2 = 0.f, den3 = 0.f;
        float a0h[4] = {0.f, 0.f, 0.f, 0.f};
        float a1h[4] = {0.f, 0.f, 0.f, 0.f};
        for (int chunk = off0; chunk < off1; chunk += 32) {
            int i = chunk + lane;
            float wx = 0.f, wy = 0.f, wz = 0.f, ww = 0.f;
            int se = 0;
            if (i < off1) {
                int e = g_eidx[i];
                float4 s = *(const float4*)(g_score + (size_t)e * 4);
                wx = __expf(s.x - mx0); wy = __expf(s.y - mx1);
                wz = __expf(s.z - mx2); ww = __expf(s.w - mx3);
                se = src[e];
            }
            den0 += wx; den1 += wy; den2 += wz; den3 += ww;
            int cnt = min(32, off1 - chunk);
            int j = 0;
            for (; j + 1 < cnt; j += 2) {
                float bx0 = __shfl_sync(0xffffffffu, wx, j);
                float by0 = __shfl_sync(0xffffffffu, wy, j);
                float bz0 = __shfl_sync(0xffffffffu, wz, j);
                float bw0 = __shfl_sync(0xffffffffu, ww, j);
                int sj0 = __shfl_sync(0xffffffffu, se, j);
                float bx1 = __shfl_sync(0xffffffffu, wx, j + 1);
                float by1 = __shfl_sync(0xffffffffu, wy, j + 1);
                float bz1 = __shfl_sync(0xffffffffu, wz, j + 1);
                float bw1 = __shfl_sync(0xffffffffu, ww, j + 1);
                int sj1 = __shfl_sync(0xffffffffu, se, j + 1);
                const float* hp0 = g_hproj + (size_t)sj0 * HC;
                const float* hp1 = g_hproj + (size_t)sj1 * HC;
                a0h[0] += hp0[lane] * bx0 + hp1[lane] * bx1;
                a0h[1] += hp0[64 + lane] * by0 + hp1[64 + lane] * by1;
                a0h[2] += hp0[128 + lane] * bz0 + hp1[128 + lane] * bz1;
                a0h[3] += hp0[192 + lane] * bw0 + hp1[192 + lane] * bw1;
                a1h[0] += hp0[32 + lane] * bx0 + hp1[32 + lane] * bx1;
                a1h[1] += hp0[96 + lane] * by0 + hp1[96 + lane] * by1;
                a1h[2] += hp0[160 + lane] * bz0 + hp1[160 + lane] * bz1;
                a1h[3] += hp0[224 + lane] * bw0 + hp1[224 + lane] * bw1;
            }
            if (j < cnt) {
                float bx = __shfl_sync(0xffffffffu, wx, j);
                float by = __shfl_sync(0xffffffffu, wy, j);
                float bz = __shfl_sync(0xffffffffu, wz, j);
                float bw = __shfl_sync(0xffffffffu, ww, j);
                int sj = __shfl_sync(0xffffffffu, se, j);
                const float* hp = g_hproj + (size_t)sj * HC;
                a0h[0] += hp[lane] * bx;
                a0h[1] += hp[64 + lane] * by;
                a0h[2] += hp[128 + lane] * bz;
                a0h[3] += hp[192 + lane] * bw;
                a1h[0] += hp[32 + lane] * bx;
                a1h[1] += hp[96 + lane] * by;
                a1h[2] += hp[160 + lane] * bz;
                a1h[3] += hp[224 + lane] * bw;
            }
        }
        den0 = warp_sum(den0); den1 = warp_sum(den1);
        den2 = warp_sum(den2); den3 = warp_sum(den3);
        float r0 = 1.f / den0, r1 = 1.f / den1, r2 = 1.f / den2, r3 = 1.f / den3;
        float m0 = 0.25f * (a0h[0] * r0 + a0h[1] * r1 + a0h[2] * r2 + a0h[3] * r3);
        float m1 = 0.25f * (a1h[0] * r0 + a1h[1] * r1 + a1h[2] * r2 + a1h[3] * r3);

        float sum = warp_sum(m0 + m1);
        float sq = warp_sum(m0 * m0 + m1 * m1);
        float mean = sum * (1.f / 64.f);
        float var = sq * (1.f / 64.f) - mean * mean;
        float rs = rsqrtf(var + 1e-5f);
        h0 = eluf((m0 - mean) * rs);
        h1 = eluf((m1 - mean) * rs);
    }

    g_h[(size_t)n * CH + lane] = h0;
    g_h[(size_t)n * CH + lane + 32] = h1;
    __nv_bfloat16 b0 = __float2bfloat16(h0);
    __nv_bfloat16 b1 = __float2bfloat16(h1);
    size_t b = (size_t)n * 128;
    g_hs[b + lane] = b0;
    g_hs[b + lane + 32] = b1;
    g_hs[b + 64 + lane] = __float2bfloat16(h0 - __bfloat162float(b0));
    g_hs[b + 96 + lane] = __float2bfloat16(h1 - __bfloat162float(b1));
}

// ---------------- fp32 SGEMM ----------------
__global__ void gemm64(const float* __restrict__ A, const float* __restrict__ B,
                       const float* __restrict__ bias, float* __restrict__ Cout,
                       __nv_bfloat16* __restrict__ Csplit,
                       int M, int K, int Nt) {
    __shared__ __align__(16) float sAt[65][68];
    __shared__ __align__(16) float sB[65][68];
    const int row0 = blockIdx.x * 64;
    const int col0 = blockIdx.y * 64;
    const int tid = threadIdx.x;

    for (int idx = tid; idx < 64 * K; idx += 256) {
        int r = idx / K, k = idx - r * K;
        sAt[k][r] = (row0 + r < M) ? A[(size_t)(row0 + r) * K + k] : 0.f;
    }
    for (int idx = tid; idx < K * 64; idx += 256) {
        int k = idx >> 6, c = idx & 63;
        sB[k][c] = B[(size_t)k * Nt + col0 + c];
    }
    __syncthreads();

    const int tx = tid & 15, ty = tid >> 4;
    float acc[4][4];
#pragma unroll
    for (int i = 0; i < 4; i++)
#pragma unroll
        for (int j = 0; j < 4; j++) acc[i][j] = 0.f;

#pragma unroll 4
    for (int k = 0; k < K; k++) {
        float4 a4 = *(const float4*)&sAt[k][ty * 4];
        float4 b4 = *(const float4*)&sB[k][tx * 4];
        float aa[4] = {a4.x, a4.y, a4.z, a4.w};
        float bb[4] = {b4.x, b4.y, b4.z, b4.w};
#pragma unroll
        for (int i = 0; i < 4; i++)
#pragma unroll
            for (int j = 0; j < 4; j++) acc[i][j] += aa[i] * bb[j];
    }
    float bv[4];
#pragma unroll
    for (int j = 0; j < 4; j++) bv[j] = bias ? bias[col0 + tx * 4 + j] : 0.f;
#pragma unroll
    for (int i = 0; i < 4; i++) {
        int r = row0 + ty * 4 + i;
        if (r < M) {
#pragma unroll
            for (int j = 0; j < 4; j++) {
                float val = acc[i][j] + bv[j];
                int col = col0 + tx * 4 + j;
                if (Cout) Cout[(size_t)r * Nt + col] = val;
                if (Csplit) {
                    __nv_bfloat16 hi = __float2bfloat16(val);
                    Csplit[(size_t)r * 128 + col] = hi;
                    Csplit[(size_t)r * 128 + 64 + col] = __float2bfloat16(val - __bfloat162float(hi));
                }
            }
        }
    }
}

// ---------------- merged preps ----------------
__global__ void prep_misc(const float* __restrict__ Wni, const float* __restrict__ Wnj,
                          const float* __restrict__ Wnode, const float* __restrict__ Wfij,
                          const float* __restrict__ We0, const float* __restrict__ be0,
                          const float* __restrict__ bias_e, const float* __restrict__ efeat) {
    int b = blockIdx.x;
    int tid = threadIdx.x;
    if (b < 1536) {
        int mat = b / 192;
        int idx = (b % 192) * 256 + tid;
        int l = mat >> 2, type = mat & 3;
        const float* W = (type == 0 ? Wni : type == 1 ? Wnj : type == 2 ? Wnode : Wfij)
                         + (size_t)l * 64 * 256;
        __nv_bfloat16* Wp = g_wprep + (size_t)mat * (256 * 192);
        int n = idx / 192, kk = idx - n * 192;
        int k = kk & 63;
        float v = W[(size_t)k * 256 + n];
        __nv_bfloat16 hi = __float2bfloat16(v);
        __nv_bfloat16 out = hi;
        if (kk >= 64 && kk < 128) out = __float2bfloat16(v - __bfloat162float(hi));
        Wp[idx] = out;
    } else if (b == 1536) {
        int n = tid;
        float col[64];
#pragma unroll
        for (int j = 0; j < 64; j++) col[j] = Wfij[j * 256 + n];
        float bs = bias_e[n];
#pragma unroll
        for (int j = 0; j < 64; j++) bs += be0[j] * col[j];
        g_bce0[n] = bs;
        for (int k = 0; k < 15; k++) {
            float s = 0.f;
#pragma unroll
            for (int j = 0; j < 64; j++) s += We0[k * 64 + j] * col[j];
            __nv_bfloat16 hi = __float2bfloat16(s);
            __nv_bfloat16 lo = __float2bfloat16(s - __bfloat162float(hi));
            g_wce0[n * 48 + k] = hi;
            g_wce0[n * 48 + 15 + k] = lo;
            g_wce0[n * 48 + 30 + k] = hi;
        }
        for (int c = 45; c < 48; c++) g_wce0[n * 48 + c] = __float2bfloat16(0.f);
    } else {
        int idx = (b - 1537) * 256 + tid;
        if (idx >= N_EDGES * 48) return;
        int e = idx / 48, c = idx - e * 48;
        __nv_bfloat16 out = __float2bfloat16(0.f);
        if (c < 45) {
            int k = c < 15 ? c : (c < 30 ? c - 15 : c - 30);
            float v = efeat[e * 15 + k];
            __nv_bfloat16 hi = __float2bfloat16(v);
            out = (c < 30) ? hi : __float2bfloat16(v - __bfloat162float(hi));
        }
        g_es[idx] = out;
    }
}

// ---------------- CSR build ----------------
__global__ void csr_zero() {
    int i = blockIdx.x * blockDim.x + threadIdx.x;
    if (i < N_NODES) g_deg[i] = 0;
}
__global__ void csr_hist(const int* __restrict__ dst) {
    int e = blockIdx.x * blockDim.x + threadIdx.x;
    if (e < N_EDGES) atomicAdd(&g_deg[dst[e]], 1);
}
__global__ void __launch_bounds__(1024) csr_scan() {
    __shared__ int ssum[1024];
    int t = threadIdx.x;
    int base = t * 20;
    int s = 0;
    int loc[20];
#pragma unroll
    for (int j = 0; j < 20; j++) {
        int idx = base + j;
        loc[j] = s;
        if (idx < N_NODES) s += g_deg[idx];
    }
    ssum[t] = s;
    __syncthreads();
    for (int o = 1; o < 1024; o <<= 1) {
        int v = (t >= o) ? ssum[t - o] : 0;
        __syncthreads();
        ssum[t] += v;
        __syncthreads();
    }
    int pre = (t == 0) ? 0 : ssum[t - 1];
#pragma unroll
    for (int j = 0; j < 20; j++) {
        int idx = base + j;
        if (idx < N_NODES) {
            int o = pre + loc[j];
            g_off[idx] = o;
            g_cursor[idx] = o;
        }
    }
    if (t == 1023) g_off[N_NODES] = ssum[1023];
}
__global__ void csr_scatter(const int* __restrict__ dst) {
    int e = blockIdx.x * blockDim.x + threadIdx.x;
    if (e >= N_EDGES) return;
    int pos = atomicAdd(&g_cursor[dst[e]], 1);
    g_eidx[pos] = e;
}

// ---------------- launcher ----------------
extern "C" void kernel_launch(void* const* d_in, const int* in_sizes, int n_in,
                              void* d_out, int out_size) {
    const float* x = (const float*)d_in[0];
    const float* efeat = (const float*)d_in[1];
    const int* src = (const int*)d_in[2];
    const int* dst = (const int*)d_in[3];
    const float* Wn0 = (const float*)d_in[4];
    const float* bn0 = (const float*)d_in[5];
    const float* We0 = (const float*)d_in[6];
    const float* be0 = (const float*)d_in[7];
    const float* Wnode = (const float*)d_in[8];
    const float* bnode = (const float*)d_in[9];
    const float* Wni = (const float*)d_in[10];
    const float* Wnj = (const float*)d_in[11];
    const float* Wfij = (const float*)d_in[12];
    const float* attn = (const float*)d_in[13];
    const float* bias_e = (const float*)d_in[14];
    const float* Wf = (const float*)d_in[15];
    const float* bf = (const float*)d_in[16];

    float *ph, *phni, *phnj, *phproj, *pbce0;
    __nv_bfloat16 *phs, *pfs, *pwp, *pes, *pwce0;
    cudaGetSymbolAddress((void**)&ph, g_h);
    cudaGetSymbolAddress((void**)&phni, g_hni);
    cudaGetSymbolAddress((void**)&phnj, g_hnj);
    cudaGetSymbolAddress((void**)&phproj, g_hproj);
    cudaGetSymbolAddress((void**)&phs, g_hs);
    cudaGetSymbolAddress((void**)&pfs, g_fs);
    cudaGetSymbolAddress((void**)&pwp, g_wprep);
    cudaGetSymbolAddress((void**)&pes, g_es);
    cudaGetSymbolAddress((void**)&pwce0, g_wce0);
    cudaGetSymbolAddress((void**)&pbce0, g_bce0);

    cudaFuncSetAttribute(gemm_node3, cudaFuncAttributeMaxDynamicSharedMemorySize, MM_SMEM);
    cudaFuncSetAttribute(gemm_edge_g2<3, 0>, cudaFuncAttributeMaxDynamicSharedMemorySize, 113664);
    cudaFuncSetAttribute(gemm_edge_g2<12, 64>, cudaFuncAttributeMaxDynamicSharedMemorySize, 224256);

    const dim3 blk(256);
    const int NB_N = (N_NODES + 63) / 64;     // 313
    const int TB_N = (N_NODES + 127) / 128;   // 157
    const int WPSZ = 256 * 192;

    // 0: node input projection
    gemm64<<<dim3(NB_N, 1), blk>>>(x, Wn0, bn0, ph, phs, N_NODES, 65, 64);
    // 1: all preps
    prep_misc<<<1537 + (N_EDGES * 48) / 256, blk>>>(Wni, Wnj, Wnode, Wfij, We0, be0, bias_e, efeat);
    // 2: layer-0 node GEMMs
    gemm_node3<<<dim3(TB_N, 3), 512, MM_SMEM>>>(phs, pwp, bnode, phni, phnj, phproj);
    // 3: layer-0 edge GEMM  <- ncu capture target
    gemm_edge_g2<3, 0><<<148, 512, 113664>>>(pes, pwce0, pbce0, attn, src, dst, NTILES64, 1);
    // 4-7: CSR build
    csr_zero<<<(N_NODES + 255) / 256, blk>>>();
    csr_hist<<<(N_EDGES + 255) / 256, blk>>>(dst);
    csr_scan<<<1, 1024>>>();
    csr_scatter<<<(N_EDGES + 255) / 256, blk>>>(dst);
    // 8: layer-0 aggregate
    node_gather<<<(N_NODES * 32 + 255) / 256, blk>>>(src);
    // 9-11: layer 1
    gemm_node3<<<dim3(TB_N, 3), 512, MM_SMEM>>>(phs, pwp + (size_t)4 * WPSZ,
                                                bnode + 256, phni, phnj, phproj);
    gemm_edge_g2<12, 64><<<148, 512, 224256>>>(pfs, pwp + (size_t)7 * WPSZ,
                                               bias_e + 256, attn + 256, src, dst, NTILES64, 0);
    node_gather<<<(N_NODES * 32 + 255) / 256, blk>>>(src);
    // 12: output projection
    gemm64<<<dim3(NB_N, 1), blk>>>(ph, Wf, bf, (float*)d_out, nullptr, N_NODES, 64, 64);
}

// round 17
// speedup vs baseline: 1.1078x; 1.1078x over previous
#include <cuda_runtime.h>
#include <cuda_bf16.h>
#include <math.h>
#include <stdint.h>

#define N_NODES 20000
#define N_EDGES 200000
#define CH 64
#define HC 256
#define NHEAD 4
#define NTILES64 3125

// ---------------- scratch ----------------
__device__ __align__(256) float    g_h[N_NODES * CH];
__device__ __align__(256) __nv_bfloat16 g_hs[N_NODES * 128];
__device__ __align__(256) __nv_bfloat16 g_fs[N_EDGES * 128];
__device__ __align__(256) __nv_bfloat16 g_es[N_EDGES * 48];
__device__ __align__(256) __nv_bfloat16 g_wprep[8 * 256 * 192];
__device__ __align__(256) __nv_bfloat16 g_wce0[256 * 48];
__device__ __align__(256) float    g_bce0[256];
__device__ __align__(256) float    g_hni[N_NODES * HC];
__device__ __align__(256) float    g_hnj[N_NODES * HC];
__device__ __align__(256) float    g_hproj[N_NODES * HC];
__device__ __align__(256) float    g_score[N_EDGES * NHEAD];
__device__ __align__(256) int g_deg[N_NODES];
__device__ __align__(256) int g_off[N_NODES + 1];
__device__ __align__(256) int g_cursor[N_NODES];
__device__ __align__(256) int g_eidx[N_EDGES];

// ---------------- helpers ----------------
__device__ __forceinline__ uint32_t smem_u32(const void* p) {
    uint32_t a;
    asm("{ .reg .u64 t; cvta.to.shared.u64 t, %1; cvt.u32.u64 %0, t; }" : "=r"(a) : "l"(p));
    return a;
}
__device__ __forceinline__ float eluf(float x) { return x > 0.f ? x : expm1f(x); }
__device__ __forceinline__ float warp_sum(float v) {
#pragma unroll
    for (int o = 16; o; o >>= 1) v += __shfl_xor_sync(0xffffffffu, v, o);
    return v;
}
__device__ __forceinline__ float warp_max(float v) {
#pragma unroll
    for (int o = 16; o; o >>= 1) v = fmaxf(v, __shfl_xor_sync(0xffffffffu, v, o));
    return v;
}
__device__ __forceinline__ void ldm_x4(uint32_t* r, uint32_t addr) {
    asm volatile("ldmatrix.sync.aligned.m8n8.x4.shared.b16 {%0,%1,%2,%3}, [%4];"
                 : "=r"(r[0]), "=r"(r[1]), "=r"(r[2]), "=r"(r[3]) : "r"(addr));
}
__device__ __forceinline__ void mma_bf16(float* d, const uint32_t* a, const uint32_t* b) {
    asm volatile("mma.sync.aligned.m16n8k16.row.col.f32.bf16.bf16.f32 "
                 "{%0,%1,%2,%3}, {%4,%5,%6,%7}, {%8,%9}, {%0,%1,%2,%3};"
                 : "+f"(d[0]), "+f"(d[1]), "+f"(d[2]), "+f"(d[3])
                 : "r"(a[0]), "r"(a[1]), "r"(a[2]), "r"(a[3]), "r"(b[0]), "r"(b[1]));
}
#define GBAR(id) asm volatile("bar.sync %0, 256;" :: "r"(id) : "memory")

#define MM_SMEM 153600

// ======== non-persistent mma tile (node GEMMs) ========
template<int KSTEPS, int HSPLIT>
__device__ __forceinline__ void mma_tile_to_stage(
    char* smem, const __nv_bfloat16* __restrict__ A, const __nv_bfloat16* __restrict__ Wp,
    int row0, int M, int tid, int w, int lane) {
    constexpr int KELEM = KSTEPS * 16;
    constexpr int STRIDE = KELEM + 8;
    constexpr int AROW = HSPLIT ? 2 * HSPLIT : KELEM;
    constexpr int CPR = KELEM / 8;
    constexpr int TILEB = 16 * STRIDE * 2;
    __nv_bfloat16* smA = (__nv_bfloat16*)smem;
    __nv_bfloat16* smB = (__nv_bfloat16*)(smem + 128 * STRIDE * 2);

    for (int u = tid; u < 128 * CPR; u += 512) {
        int m = u / CPR, k0 = (u % CPR) * 8;
        int sc = (HSPLIT && k0 >= HSPLIT) ? k0 - HSPLIT : k0;
        int mm = row0 + m < M ? row0 + m : M - 1;
        int bytes = (row0 + m < M) ? 16 : 0;
        uint32_t sa = smem_u32(smA + m * STRIDE + k0);
        asm volatile("cp.async.cg.shared.global [%0], [%1], 16, %2;"
                     :: "r"(sa), "l"(A + (size_t)mm * AROW + sc), "r"(bytes));
    }
    for (int u = tid; u < 256 * CPR; u += 512) {
        int n = u / CPR, k0 = (u % CPR) * 8;
        uint32_t sa = smem_u32(smB + n * STRIDE + k0);
        asm volatile("cp.async.cg.shared.global [%0], [%1], 16;"
                     :: "r"(sa), "l"(Wp + (size_t)n * KELEM + k0));
    }
    asm volatile("cp.async.commit_group;");
    asm volatile("cp.async.wait_group 0;" ::: "memory");
    __syncthreads();

    const int mw = (w >> 3) * 64;
    const int nw = (w & 7) * 32;
    const int g = lane >> 3, r = lane & 7;

    float acc[4][4][4];
#pragma unroll
    for (int i = 0; i < 4; i++)
#pragma unroll
        for (int j = 0; j < 4; j++)
#pragma unroll
            for (int q = 0; q < 4; q++) acc[i][j][q] = 0.f;

    uint32_t aAddr = smem_u32(smA) + ((mw + (g & 1) * 8 + r) * STRIDE + (g >> 1) * 8) * 2;
    uint32_t bAddr = smem_u32(smB) + ((nw + (g >> 1) * 8 + r) * STRIDE + (g & 1) * 8) * 2;

#pragma unroll
    for (int ks = 0; ks < KSTEPS; ks++) {
        uint32_t af[4][4], bf[2][4];
#pragma unroll
        for (int i = 0; i < 4; i++) ldm_x4(af[i], aAddr + i * TILEB);
#pragma unroll
        for (int p = 0; p < 2; p++) ldm_x4(bf[p], bAddr + p * TILEB);
#pragma unroll
        for (int i = 0; i < 4; i++)
#pragma unroll
            for (int j = 0; j < 4; j++)
                mma_bf16(acc[i][j], af[i], &bf[j >> 1][(j & 1) * 2]);
        aAddr += 32;
        bAddr += 32;
    }

    __syncthreads();
    float* stage = (float*)smem;
#pragma unroll
    for (int i = 0; i < 4; i++)
#pragma unroll
        for (int j = 0; j < 4; j++) {
            int m = mw + i * 16 + (lane >> 2);
            int n = nw + j * 8 + (lane & 3) * 2;
            stage[m * 260 + n] = acc[i][j][0];
            stage[m * 260 + n + 1] = acc[i][j][1];
            stage[(m + 8) * 260 + n] = acc[i][j][2];
            stage[(m + 8) * 260 + n + 1] = acc[i][j][3];
        }
}

// ======== node GEMMs: ni, nj, node(hproj)+bias ========
__global__ void __launch_bounds__(512, 1)
gemm_node3(const __nv_bfloat16* __restrict__ A, const __nv_bfloat16* __restrict__ WpBase,
           const float* __restrict__ bnode_l,
           float* __restrict__ Cni, float* __restrict__ Cnj, float* __restrict__ Cnode) {
    extern __shared__ __align__(1024) char smem[];
    const int tid = threadIdx.x, w = tid >> 5, lane = tid & 31;
    const int row0 = blockIdx.x * 128;
    const int y = blockIdx.y;
    const __nv_bfloat16* Wp = WpBase + (size_t)y * (256 * 192);
    float* C = (y == 0) ? Cni : (y == 1) ? Cnj : Cnode;
    const float* bias = (y == 2) ? bnode_l : nullptr;

    mma_tile_to_stage<12, 64>(smem, A, Wp, row0, N_NODES, tid, w, lane);
    __syncthreads();

    float* stage = (float*)smem;
    int rows = min(128, N_NODES - row0);
    for (int u = tid; u < rows * 64; u += 512) {
        int m2 = u >> 6, c4 = (u & 63) * 4;
        float4 v = *(float4*)(stage + m2 * 260 + c4);
        if (bias) {
            float4 bb = *(const float4*)(bias + c4);
            v.x += bb.x; v.y += bb.y; v.z += bb.z; v.w += bb.w;
        }
        *(float4*)(C + (size_t)(row0 + m2) * 256 + c4) = v;
    }
}

// ======== batch-2 per-edge finisher (WRITEF compile-time) ========
template<int WRITEF>
__device__ __forceinline__ void edge_finish2(
    int e0, int e1, bool ok1, float* v0, float* v1,
    const float* sAttn, int lane) {
    float p[2][NHEAD];
#pragma unroll
    for (int h = 0; h < NHEAD; h++) {
        float a0 = sAttn[h * 64 + lane];
        float a1 = sAttn[h * 64 + lane + 32];
        float x00 = v0[2 * h], x01 = v0[2 * h + 1];
        float x10 = v1[2 * h], x11 = v1[2 * h + 1];
        float l00 = x00 > 0.f ? x00 : 0.01f * x00;
        float l01 = x01 > 0.f ? x01 : 0.01f * x01;
        float l10 = x10 > 0.f ? x10 : 0.01f * x10;
        float l11 = x11 > 0.f ? x11 : 0.01f * x11;
        p[0][h] = l00 * a0 + l01 * a1;
        p[1][h] = l10 * a0 + l11 * a1;
    }
#pragma unroll
    for (int o = 16; o; o >>= 1)
#pragma unroll
        for (int q = 0; q < 2; q++)
#pragma unroll
            for (int h = 0; h < NHEAD; h++)
                p[q][h] += __shfl_xor_sync(0xffffffffu, p[q][h], o);
    if (lane < NHEAD) {
        g_score[e0 * NHEAD + lane] = p[0][lane];
        if (ok1) g_score[e1 * NHEAD + lane] = p[1][lane];
    }

    if (WRITEF) {
        float m00 = 0.25f * (v0[0] + v0[2] + v0[4] + v0[6]);
        float m01 = 0.25f * (v0[1] + v0[3] + v0[5] + v0[7]);
        float m10 = 0.25f * (v1[0] + v1[2] + v1[4] + v1[6]);
        float m11 = 0.25f * (v1[1] + v1[3] + v1[5] + v1[7]);
        float su0 = m00 + m01, sq0 = m00 * m00 + m01 * m01;
        float su1 = m10 + m11, sq1 = m10 * m10 + m11 * m11;
#pragma unroll
        for (int o = 16; o; o >>= 1) {
            su0 += __shfl_xor_sync(0xffffffffu, su0, o);
            sq0 += __shfl_xor_sync(0xffffffffu, sq0, o);
            su1 += __shfl_xor_sync(0xffffffffu, su1, o);
            sq1 += __shfl_xor_sync(0xffffffffu, sq1, o);
        }
        {
            float mean = su0 * (1.f / 64.f);
            float var = sq0 * (1.f / 64.f) - mean * mean;
            float rs = rsqrtf(var + 1e-5f);
            float f0 = eluf((m00 - mean) * rs);
            float f1 = eluf((m01 - mean) * rs);
            __nv_bfloat16 h0 = __float2bfloat16(f0);
            __nv_bfloat16 h1 = __float2bfloat16(f1);
            size_t b = (size_t)e0 * 128;
            g_fs[b + lane] = h0;
            g_fs[b + lane + 32] = h1;
            g_fs[b + 64 + lane] = __float2bfloat16(f0 - __bfloat162float(h0));
            g_fs[b + 96 + lane] = __float2bfloat16(f1 - __bfloat162float(h1));
        }
        if (ok1) {
            float mean = su1 * (1.f / 64.f);
            float var = sq1 * (1.f / 64.f) - mean * mean;
            float rs = rsqrtf(var + 1e-5f);
            float f0 = eluf((m10 - mean) * rs);
            float f1 = eluf((m11 - mean) * rs);
            __nv_bfloat16 h0 = __float2bfloat16(f0);
            __nv_bfloat16 h1 = __float2bfloat16(f1);
            size_t b = (size_t)e1 * 128;
            g_fs[b + lane] = h0;
            g_fs[b + lane + 32] = h1;
            g_fs[b + 64 + lane] = __float2bfloat16(f0 - __bfloat162float(h0));
            g_fs[b + 96 + lane] = __float2bfloat16(f1 - __bfloat162float(h1));
        }
    }
}

// ======== DUAL-GROUP persistent edge GEMM: 2 independent 8-warp pipelines, shared B ========
template<int KSTEPS, int HSPLIT, int WRITEF>
__global__ void __launch_bounds__(512)
gemm_edge_g2(const __nv_bfloat16* __restrict__ A, const __nv_bfloat16* __restrict__ Wp,
             const float* __restrict__ bias_e_l, const float* __restrict__ attn_l,
             const int* __restrict__ src, const int* __restrict__ dst,
             int numTiles) {
    constexpr int KELEM = KSTEPS * 16;
    constexpr int STRIDE = KELEM + 8;
    constexpr int AROW = HSPLIT ? 2 * HSPLIT : KELEM;
    constexpr int CPR = KELEM / 8;
    constexpr int TILEB = 16 * STRIDE * 2;
    constexpr int OFF_G = 256 * STRIDE * 2;
    constexpr int ASZ = 64 * STRIDE * 2;
    constexpr int GSZ = ASZ + 33280 + 1024;
    constexpr int OFF_ATTN = OFF_G + 2 * GSZ;
    constexpr int OFF_BIAS = OFF_ATTN + 1024;
    extern __shared__ __align__(1024) char smem[];
    const int tid = threadIdx.x;
    const int grp = tid >> 8;
    const int gtid = tid & 255;
    const int lw = (tid >> 5) & 7;
    const int lane = tid & 31;

    __nv_bfloat16* smB = (__nv_bfloat16*)smem;
    char* gbase = smem + OFF_G + grp * GSZ;
    __nv_bfloat16* smA = (__nv_bfloat16*)gbase;
    float* stage = (float*)(gbase + ASZ);
    int* sSrc = (int*)(gbase + ASZ + 33280);
    int* sDst = sSrc + 128;
    float* sAttn = (float*)(smem + OFF_ATTN);
    float* sBias = (float*)(smem + OFF_BIAS);

    for (int u = tid; u < 256 * CPR; u += 512) {
        int n = u / CPR, k0 = (u % CPR) * 8;
        uint32_t sa = smem_u32(smB + n * STRIDE + k0);
        asm volatile("cp.async.cg.shared.global [%0], [%1], 16;"
                     :: "r"(sa), "l"(Wp + (size_t)n * KELEM + k0));
    }
    if (tid < 256) sAttn[tid] = attn_l[tid];
    else sBias[tid - 256] = bias_e_l[tid - 256];

    auto fillA = [&](int t, int par) {
        int row0 = t * 64;
        for (int u = gtid; u < 64 * CPR; u += 256) {
            int m = u / CPR, k0 = (u % CPR) * 8;
            int sc = (HSPLIT && k0 >= HSPLIT) ? k0 - HSPLIT : k0;
            int mm = row0 + m < N_EDGES ? row0 + m : N_EDGES - 1;
            int bytes = (row0 + m < N_EDGES) ? 16 : 0;
            uint32_t sa = smem_u32(smA + m * STRIDE + k0);
            asm volatile("cp.async.cg.shared.global [%0], [%1], 16, %2;"
                         :: "r"(sa), "l"(A + (size_t)mm * AROW + sc), "r"(bytes));
        }
        if (gtid < 32) {
            int c = gtid & 15;
            int isd = gtid >> 4;
            const int* gp = isd ? dst : src;
            int eo = row0 + c * 4;
            int bytes = (eo + 4 <= N_EDGES) ? 16 : 0;
            int eoc = eo + 4 <= N_EDGES ? eo : 0;
            uint32_t sa = smem_u32((isd ? sDst : sSrc) + par * 64 + c * 4);
            asm volatile("cp.async.ca.shared.global [%0], [%1], 16, %2;"
                         :: "r"(sa), "l"(gp + eoc), "r"(bytes));
        }
        asm volatile("cp.async.commit_group;");
    };

    const int stride = gridDim.x * 2;
    int t = blockIdx.x * 2 + grp;
    int par = 0;
    if (t < numTiles) fillA(t, par);
    else asm volatile("cp.async.commit_group;");
    asm volatile("cp.async.wait_group 0;" ::: "memory");
    __syncthreads();

    const int mw = (lw >> 2) * 32;
    const int nw = (lw & 3) * 64;
    const int l8 = lane >> 3, r = lane & 7;
    const int barid = 1 + grp;

    for (; t < numTiles; t += stride) {
        int row0 = t * 64;

        float acc[2][8][4];
#pragma unroll
        for (int i = 0; i < 2; i++)
#pragma unroll
            for (int j = 0; j < 8; j++)
#pragma unroll
                for (int q = 0; q < 4; q++) acc[i][j][q] = 0.f;

        uint32_t aAddr = smem_u32(smA) + ((mw + (l8 & 1) * 8 + r) * STRIDE + (l8 >> 1) * 8) * 2;
        uint32_t bAddr = smem_u32(smB) + ((nw + (l8 >> 1) * 8 + r) * STRIDE + (l8 & 1) * 8) * 2;
#pragma unroll
        for (int ks = 0; ks < KSTEPS; ks++) {
            uint32_t af[2][4], bf[4][4];
#pragma unroll
            for (int i = 0; i < 2; i++) ldm_x4(af[i], aAddr + i * TILEB);
#pragma unroll
            for (int p = 0; p < 4; p++) ldm_x4(bf[p], bAddr + p * TILEB);
#pragma unroll
            for (int i = 0; i < 2; i++)
#pragma unroll
                for (int j = 0; j < 8; j++)
                    mma_bf16(acc[i][j], af[i], &bf[j >> 1][(j & 1) * 2]);
            aAddr += 32;
            bAddr += 32;
        }
        GBAR(barid);

        int nxt = t + stride;
        if (nxt < numTiles) fillA(nxt, par ^ 1);

#pragma unroll
        for (int c = 0; c < 2; c++) {
            if ((lw >> 2) == c) {
#pragma unroll
                for (int i = 0; i < 2; i++)
#pragma unroll
                    for (int j = 0; j < 8; j++) {
                        int m = i * 16 + (lane >> 2);
                        int n = nw + j * 8 + (lane & 3) * 2;
                        stage[m * 260 + n] = acc[i][j][0];
                        stage[m * 260 + n + 1] = acc[i][j][1];
                        stage[(m + 8) * 260 + n] = acc[i][j][2];
                        stage[(m + 8) * 260 + n + 1] = acc[i][j][3];
                    }
            }
            GBAR(barid);

            for (int k = 0; k < 4; k += 2) {
                int rl = lw * 4 + k;
                int el = c * 32 + rl;
                int e0 = row0 + el, e1 = e0 + 1;
                if (e0 >= N_EDGES) continue;
                bool ok1 = (e1 < N_EDGES);
                int s0 = sSrc[par * 64 + el], d0 = sDst[par * 64 + el];
                int s1 = sSrc[par * 64 + el + 1], d1 = sDst[par * 64 + el + 1];
                const float* pni0 = g_hni + (size_t)s0 * HC;
                const float* pnj0 = g_hnj + (size_t)d0 * HC;
                const float* pni1 = g_hni + (size_t)s1 * HC;
                const float* pnj1 = g_hnj + (size_t)d1 * HC;
                float v0[8], v1[8];
#pragma unroll
                for (int j = 0; j < 8; j++) {
                    int cc = lane + 32 * j;
                    v0[j] = stage[rl * 260 + cc] + pni0[cc] + pnj0[cc] + sBias[cc];
                    v1[j] = stage[(rl + 1) * 260 + cc] + pni1[cc] + pnj1[cc] + sBias[cc];
                }
                edge_finish2<WRITEF>(e0, e1, ok1, v0, v1, sAttn, lane);
            }
            GBAR(barid);
        }

        if (nxt < numTiles) {
            asm volatile("cp.async.wait_group 0;" ::: "memory");
        }
        GBAR(barid);
        par ^= 1;
    }
}

// ======== node gather ========
__global__ void __launch_bounds__(256)
node_gather(const int* __restrict__ src) {
    int n = (blockIdx.x * blockDim.x + threadIdx.x) >> 5;
    if (n >= N_NODES) return;
    int lane = threadIdx.x & 31;
    int off0 = g_off[n], off1 = g_off[n + 1];

    float h0 = 0.f, h1 = 0.f;
    if (off0 < off1) {
        float mx0 = -1e30f, mx1 = -1e30f, mx2 = -1e30f, mx3 = -1e30f;
        for (int i = off0 + lane; i < off1; i += 32) {
            int e = g_eidx[i];
            float4 s = *(const float4*)(g_score + (size_t)e * 4);
            mx0 = fmaxf(mx0, s.x); mx1 = fmaxf(mx1, s.y);
            mx2 = fmaxf(mx2, s.z); mx3 = fmaxf(mx3, s.w);
        }
        mx0 = warp_max(mx0); mx1 = warp_max(mx1);
        mx2 = warp_max(mx2); mx3 = warp_max(mx3);

        float den0 = 0.f, den1 = 0.f, den2 = 0.f, den3 = 0.f;
        float a0h[4] = {0.f, 0.f, 0.f, 0.f};
        float a1h[4] = {0.f, 0.f, 0.f, 0.f};
        for (int chunk = off0; chunk < off1; chunk += 32) {
            int i = chunk + lane;
            float wx = 0.f, wy = 0.f, wz = 0.f, ww = 0.f;
            int se = 0;
            if (i < off1) {
                int e = g_eidx[i];
                float4 s = *(const float4*)(g_score + (size_t)e * 4);
                wx = __expf(s.x - mx0); wy = __expf(s.y - mx1);
                wz = __expf(s.z - mx2); ww = __expf(s.w - mx3);
                se = src[e];
            }
            den0 += wx; den1 += wy; den2 += wz; den3 += ww;
            int cnt = min(32, off1 - chunk);
            int j = 0;
            for (; j + 1 < cnt; j += 2) {
                float bx0 = __shfl_sync(0xffffffffu, wx, j);
                float by0 = __shfl_sync(0xffffffffu, wy, j);
                float bz0 = __shfl_sync(0xffffffffu, wz, j);
                float bw0 = __shfl_sync(0xffffffffu, ww, j);
                int sj0 = __shfl_sync(0xffffffffu, se, j);
                float bx1 = __shfl_sync(0xffffffffu, wx, j + 1);
                float by1 = __shfl_sync(0xffffffffu, wy, j + 1);
                float bz1 = __shfl_sync(0xffffffffu, wz, j + 1);
                float bw1 = __shfl_sync(0xffffffffu, ww, j + 1);
                int sj1 = __shfl_sync(0xffffffffu, se, j + 1);
                const float* hp0 = g_hproj + (size_t)sj0 * HC;
                const float* hp1 = g_hproj + (size_t)sj1 * HC;
                a0h[0] += hp0[lane] * bx0 + hp1[lane] * bx1;
                a0h[1] += hp0[64 + lane] * by0 + hp1[64 + lane] * by1;
                a0h[2] += hp0[128 + lane] * bz0 + hp1[128 + lane] * bz1;
                a0h[3] += hp0[192 + lane] * bw0 + hp1[192 + lane] * bw1;
                a1h[0] += hp0[32 + lane] * bx0 + hp1[32 + lane] * bx1;
                a1h[1] += hp0[96 + lane] * by0 + hp1[96 + lane] * by1;
                a1h[2] += hp0[160 + lane] * bz0 + hp1[160 + lane] * bz1;
                a1h[3] += hp0[224 + lane] * bw0 + hp1[224 + lane] * bw1;
            }
            if (j < cnt) {
                float bx = __shfl_sync(0xffffffffu, wx, j);
                float by = __shfl_sync(0xffffffffu, wy, j);
                float bz = __shfl_sync(0xffffffffu, wz, j);
                float bw = __shfl_sync(0xffffffffu, ww, j);
                int sj = __shfl_sync(0xffffffffu, se, j);
                const float* hp = g_hproj + (size_t)sj * HC;
                a0h[0] += hp[lane] * bx;
                a0h[1] += hp[64 + lane] * by;
                a0h[2] += hp[128 + lane] * bz;
                a0h[3] += hp[192 + lane] * bw;
                a1h[0] += hp[32 + lane] * bx;
                a1h[1] += hp[96 + lane] * by;
                a1h[2] += hp[160 + lane] * bz;
                a1h[3] += hp[224 + lane] * bw;
            }
        }
        den0 = warp_sum(den0); den1 = warp_sum(den1);
        den2 = warp_sum(den2); den3 = warp_sum(den3);
        float r0 = 1.f / den0, r1 = 1.f / den1, r2 = 1.f / den2, r3 = 1.f / den3;
        float m0 = 0.25f * (a0h[0] * r0 + a0h[1] * r1 + a0h[2] * r2 + a0h[3] * r3);
        float m1 = 0.25f * (a1h[0] * r0 + a1h[1] * r1 + a1h[2] * r2 + a1h[3] * r3);

        float sum = warp_sum(m0 + m1);
        float sq = warp_sum(m0 * m0 + m1 * m1);
        float mean = sum * (1.f / 64.f);
        float var = sq * (1.f / 64.f) - mean * mean;
        float rs = rsqrtf(var + 1e-5f);
        h0 = eluf((m0 - mean) * rs);
        h1 = eluf((m1 - mean) * rs);
    }

    g_h[(size_t)n * CH + lane] = h0;
    g_h[(size_t)n * CH + lane + 32] = h1;
    __nv_bfloat16 b0 = __float2bfloat16(h0);
    __nv_bfloat16 b1 = __float2bfloat16(h1);
    size_t b = (size_t)n * 128;
    g_hs[b + lane] = b0;
    g_hs[b + lane + 32] = b1;
    g_hs[b + 64 + lane] = __float2bfloat16(h0 - __bfloat162float(b0));
    g_hs[b + 96 + lane] = __float2bfloat16(h1 - __bfloat162float(b1));
}

// ---------------- fp32 SGEMM ----------------
__global__ void gemm64(const float* __restrict__ A, const float* __restrict__ B,
                       const float* __restrict__ bias, float* __restrict__ Cout,
                       __nv_bfloat16* __restrict__ Csplit,
                       int M, int K, int Nt) {
    __shared__ __align__(16) float sAt[65][68];
    __shared__ __align__(16) float sB[65][68];
    const int row0 = blockIdx.x * 64;
    const int col0 = blockIdx.y * 64;
    const int tid = threadIdx.x;

    for (int idx = tid; idx < 64 * K; idx += 256) {
        int r = idx / K, k = idx - r * K;
        sAt[k][r] = (row0 + r < M) ? A[(size_t)(row0 + r) * K + k] : 0.f;
    }
    for (int idx = tid; idx < K * 64; idx += 256) {
        int k = idx >> 6, c = idx & 63;
        sB[k][c] = B[(size_t)k * Nt + col0 + c];
    }
    __syncthreads();

    const int tx = tid & 15, ty = tid >> 4;
    float acc[4][4];
#pragma unroll
    for (int i = 0; i < 4; i++)
#pragma unroll
        for (int j = 0; j < 4; j++) acc[i][j] = 0.f;

#pragma unroll 4
    for (int k = 0; k < K; k++) {
        float4 a4 = *(const float4*)&sAt[k][ty * 4];
        float4 b4 = *(const float4*)&sB[k][tx * 4];
        float aa[4] = {a4.x, a4.y, a4.z, a4.w};
        float bb[4] = {b4.x, b4.y, b4.z, b4.w};
#pragma unroll
        for (int i = 0; i < 4; i++)
#pragma unroll
            for (int j = 0; j < 4; j++) acc[i][j] += aa[i] * bb[j];
    }
    float bv[4];
#pragma unroll
    for (int j = 0; j < 4; j++) bv[j] = bias ? bias[col0 + tx * 4 + j] : 0.f;
#pragma unroll
    for (int i = 0; i < 4; i++) {
        int r = row0 + ty * 4 + i;
        if (r < M) {
#pragma unroll
            for (int j = 0; j < 4; j++) {
                float val = acc[i][j] + bv[j];
                int col = col0 + tx * 4 + j;
                if (Cout) Cout[(size_t)r * Nt + col] = val;
                if (Csplit) {
                    __nv_bfloat16 hi = __float2bfloat16(val);
                    Csplit[(size_t)r * 128 + col] = hi;
                    Csplit[(size_t)r * 128 + 64 + col] = __float2bfloat16(val - __bfloat162float(hi));
                }
            }
        }
    }
}

// ---------------- merged preps ----------------
__global__ void prep_misc(const float* __restrict__ Wni, const float* __restrict__ Wnj,
                          const float* __restrict__ Wnode, const float* __restrict__ Wfij,
                          const float* __restrict__ We0, const float* __restrict__ be0,
                          const float* __restrict__ bias_e, const float* __restrict__ efeat) {
    int b = blockIdx.x;
    int tid = threadIdx.x;
    if (b < 1536) {
        int mat = b / 192;
        int idx = (b % 192) * 256 + tid;
        int l = mat >> 2, type = mat & 3;
        const float* W = (type == 0 ? Wni : type == 1 ? Wnj : type == 2 ? Wnode : Wfij)
                         + (size_t)l * 64 * 256;
        __nv_bfloat16* Wp = g_wprep + (size_t)mat * (256 * 192);
        int n = idx / 192, kk = idx - n * 192;
        int k = kk & 63;
        float v = W[(size_t)k * 256 + n];
        __nv_bfloat16 hi = __float2bfloat16(v);
        __nv_bfloat16 out = hi;
        if (kk >= 64 && kk < 128) out = __float2bfloat16(v - __bfloat162float(hi));
        Wp[idx] = out;
    } else if (b == 1536) {
        int n = tid;
        float col[64];
#pragma unroll
        for (int j = 0; j < 64; j++) col[j] = Wfij[j * 256 + n];
        float bs = bias_e[n];
#pragma unroll
        for (int j = 0; j < 64; j++) bs += be0[j] * col[j];
        g_bce0[n] = bs;
        for (int k = 0; k < 15; k++) {
            float s = 0.f;
#pragma unroll
            for (int j = 0; j < 64; j++) s += We0[k * 64 + j] * col[j];
            __nv_bfloat16 hi = __float2bfloat16(s);
            __nv_bfloat16 lo = __float2bfloat16(s - __bfloat162float(hi));
            g_wce0[n * 48 + k] = hi;
            g_wce0[n * 48 + 15 + k] = lo;
            g_wce0[n * 48 + 30 + k] = hi;
        }
        for (int c = 45; c < 48; c++) g_wce0[n * 48 + c] = __float2bfloat16(0.f);
    } else {
        int idx = (b - 1537) * 256 + tid;
        if (idx >= N_EDGES * 48) return;
        int e = idx / 48, c = idx - e * 48;
        __nv_bfloat16 out = __float2bfloat16(0.f);
        if (c < 45) {
            int k = c < 15 ? c : (c < 30 ? c - 15 : c - 30);
            float v = efeat[e * 15 + k];
            __nv_bfloat16 hi = __float2bfloat16(v);
            out = (c < 30) ? hi : __float2bfloat16(v - __bfloat162float(hi));
        }
        g_es[idx] = out;
    }
}

// ---------------- CSR build ----------------
__global__ void csr_zero() {
    int i = blockIdx.x * blockDim.x + threadIdx.x;
    if (i < N_NODES) g_deg[i] = 0;
}
__global__ void csr_hist(const int* __restrict__ dst) {
    int e = blockIdx.x * blockDim.x + threadIdx.x;
    if (e < N_EDGES) atomicAdd(&g_deg[dst[e]], 1);
}
__global__ void __launch_bounds__(1024) csr_scan() {
    __shared__ int ssum[1024];
    int t = threadIdx.x;
    int base = t * 20;
    int s = 0;
    int loc[20];
#pragma unroll
    for (int j = 0; j < 20; j++) {
        int idx = base + j;
        loc[j] = s;
        if (idx < N_NODES) s += g_deg[idx];
    }
    ssum[t] = s;
    __syncthreads();
    for (int o = 1; o < 1024; o <<= 1) {
        int v = (t >= o) ? ssum[t - o] : 0;
        __syncthreads();
        ssum[t] += v;
        __syncthreads();
    }
    int pre = (t == 0) ? 0 : ssum[t - 1];
#pragma unroll
    for (int j = 0; j < 20; j++) {
        int idx = base + j;
        if (idx < N_NODES) {
            int o = pre + loc[j];
            g_off[idx] = o;
            g_cursor[idx] = o;
        }
    }
    if (t == 1023) g_off[N_NODES] = ssum[1023];
}
__global__ void csr_scatter(const int* __restrict__ dst) {
    int e = blockIdx.x * blockDim.x + threadIdx.x;
    if (e >= N_EDGES) return;
    int pos = atomicAdd(&g_cursor[dst[e]], 1);
    g_eidx[pos] = e;
}

// ---------------- launcher ----------------
extern "C" void kernel_launch(void* const* d_in, const int* in_sizes, int n_in,
                              void* d_out, int out_size) {
    const float* x = (const float*)d_in[0];
    const float* efeat = (const float*)d_in[1];
    const int* src = (const int*)d_in[2];
    const int* dst = (const int*)d_in[3];
    const float* Wn0 = (const float*)d_in[4];
    const float* bn0 = (const float*)d_in[5];
    const float* We0 = (const float*)d_in[6];
    const float* be0 = (const float*)d_in[7];
    const float* Wnode = (const float*)d_in[8];
    const float* bnode = (const float*)d_in[9];
    const float* Wni = (const float*)d_in[10];
    const float* Wnj = (const float*)d_in[11];
    const float* Wfij = (const float*)d_in[12];
    const float* attn = (const float*)d_in[13];
    const float* bias_e = (const float*)d_in[14];
    const float* Wf = (const float*)d_in[15];
    const float* bf = (const float*)d_in[16];

    float *ph, *phni, *phnj, *phproj, *pbce0;
    __nv_bfloat16 *phs, *pfs, *pwp, *pes, *pwce0;
    cudaGetSymbolAddress((void**)&ph, g_h);
    cudaGetSymbolAddress((void**)&phni, g_hni);
    cudaGetSymbolAddress((void**)&phnj, g_hnj);
    cudaGetSymbolAddress((void**)&phproj, g_hproj);
    cudaGetSymbolAddress((void**)&phs, g_hs);
    cudaGetSymbolAddress((void**)&pfs, g_fs);
    cudaGetSymbolAddress((void**)&pwp, g_wprep);
    cudaGetSymbolAddress((void**)&pes, g_es);
    cudaGetSymbolAddress((void**)&pwce0, g_wce0);
    cudaGetSymbolAddress((void**)&pbce0, g_bce0);

    cudaFuncSetAttribute(gemm_node3, cudaFuncAttributeMaxDynamicSharedMemorySize, MM_SMEM);
    cudaFuncSetAttribute(gemm_edge_g2<3, 0, 1>, cudaFuncAttributeMaxDynamicSharedMemorySize, 113664);
    cudaFuncSetAttribute(gemm_edge_g2<12, 64, 0>, cudaFuncAttributeMaxDynamicSharedMemorySize, 224256);

    const dim3 blk(256);
    const int NB_N = (N_NODES + 63) / 64;     // 313
    const int TB_N = (N_NODES + 127) / 128;   // 157
    const int WPSZ = 256 * 192;

    // 0: node input projection
    gemm64<<<dim3(NB_N, 1), blk>>>(x, Wn0, bn0, ph, phs, N_NODES, 65, 64);
    // 1: all preps
    prep_misc<<<1537 + (N_EDGES * 48) / 256, blk>>>(Wni, Wnj, Wnode, Wfij, We0, be0, bias_e, efeat);
    // 2: layer-0 node GEMMs
    gemm_node3<<<dim3(TB_N, 3), 512, MM_SMEM>>>(phs, pwp, bnode, phni, phnj, phproj);
    // 3: layer-0 edge GEMM  <- ncu capture target
    gemm_edge_g2<3, 0, 1><<<148, 512, 113664>>>(pes, pwce0, pbce0, attn, src, dst, NTILES64);
    // 4-7: CSR build
    csr_zero<<<(N_NODES + 255) / 256, blk>>>();
    csr_hist<<<(N_EDGES + 255) / 256, blk>>>(dst);
    csr_scan<<<1, 1024>>>();
    csr_scatter<<<(N_EDGES + 255) / 256, blk>>>(dst);
    // 8: layer-0 aggregate
    node_gather<<<(N_NODES * 32 + 255) / 256, blk>>>(src);
    // 9-11: layer 1
    gemm_node3<<<dim3(TB_N, 3), 512, MM_SMEM>>>(phs, pwp + (size_t)4 * WPSZ,
                                                bnode + 256, phni, phnj, phproj);
    gemm_edge_g2<12, 64, 0><<<148, 512, 224256>>>(pfs, pwp + (size_t)7 * WPSZ,
                                                  bias_e + 256, attn + 256, src, dst, NTILES64);
    node_gather<<<(N_NODES * 32 + 255) / 256, blk>>>(src);
    // 12: output projection
    gemm64<<<dim3(NB_N, 1), blk>>>(ph, Wf, bf, (float*)d_out, nullptr, N_NODES, 64, 64);
}